// round 1
// baseline (speedup 1.0000x reference)
#include <cuda_runtime.h>
#include <math.h>

// Problem constants
#define BATCH 4
#define SEQ 2048
#define NWIRES 8
#define EMBED 512
#define HEADS 8
#define DK 64
#define TOKENS (BATCH * SEQ)          // 8192
#define BH (BATCH * HEADS)            // 32

// scale folded into q: 1/sqrt(64) * log2(e)
#define QSCALE (0.125f * 1.4426950408889634f)

// Scratch (device globals; allocation-free rule)
__device__ float g_q[BH * SEQ * DK];    // [bh][s][d]
__device__ float g_k[BH * SEQ * DK];
__device__ float g_v[BH * SEQ * DK];
__device__ float g_ao[TOKENS * EMBED];  // attention output [t][e], e = h*64+d

// ---------------------------------------------------------------------------
// Kernel 1: proj = cos(x + theta); q/k/v = proj @ W^T, scatter to [bh][s][d]
// block: 512 threads, 16 tokens per block. W rows live in registers.
// ---------------------------------------------------------------------------
__global__ void __launch_bounds__(512) qkv_kernel(
    const float* __restrict__ x, const float* __restrict__ theta,
    const float* __restrict__ Wq, const float* __restrict__ Wk,
    const float* __restrict__ Wv)
{
    __shared__ float sproj[16][NWIRES];
    const int tid = threadIdx.x;
    const int t0 = blockIdx.x * 16;

    if (tid < 16 * NWIRES) {
        int tl = tid >> 3, n = tid & 7;
        sproj[tl][n] = cosf(x[(t0 + tl) * NWIRES + n] + theta[n]);
    }
    __syncthreads();

    const int e = tid;                // embed index 0..511
    const int h = e >> 6, d = e & 63;

    // load weight rows (8 floats each) into registers, coalesced float4
    float4 wq0 = ((const float4*)(Wq + e * 8))[0];
    float4 wq1 = ((const float4*)(Wq + e * 8))[1];
    float4 wk0 = ((const float4*)(Wk + e * 8))[0];
    float4 wk1 = ((const float4*)(Wk + e * 8))[1];
    float4 wv0 = ((const float4*)(Wv + e * 8))[0];
    float4 wv1 = ((const float4*)(Wv + e * 8))[1];

    #pragma unroll 4
    for (int tl = 0; tl < 16; tl++) {
        float p0 = sproj[tl][0], p1 = sproj[tl][1], p2 = sproj[tl][2], p3 = sproj[tl][3];
        float p4 = sproj[tl][4], p5 = sproj[tl][5], p6 = sproj[tl][6], p7 = sproj[tl][7];
        float q = p0*wq0.x + p1*wq0.y + p2*wq0.z + p3*wq0.w
                + p4*wq1.x + p5*wq1.y + p6*wq1.z + p7*wq1.w;
        float k = p0*wk0.x + p1*wk0.y + p2*wk0.z + p3*wk0.w
                + p4*wk1.x + p5*wk1.y + p6*wk1.z + p7*wk1.w;
        float v = p0*wv0.x + p1*wv0.y + p2*wv0.z + p3*wv0.w
                + p4*wv1.x + p5*wv1.y + p6*wv1.z + p7*wv1.w;
        int t = t0 + tl;
        int b = t >> 11, s = t & 2047;
        int idx = ((b * HEADS + h) * SEQ + s) * DK + d;
        g_q[idx] = q * QSCALE;
        g_k[idx] = k;
        g_v[idx] = v;
    }
}

// ---------------------------------------------------------------------------
// Kernel 2: flash attention, fp32. One block = 128 q-rows of one (b,h).
// K/V tiles of 32 rows staged in shared; scores in padded shared.
// ---------------------------------------------------------------------------
#define KTILE 32

__global__ void __launch_bounds__(128, 2) attn_kernel()
{
    __shared__ float4 sK[KTILE][16];
    __shared__ float4 sV[KTILE][16];
    __shared__ float  sS[128][33];   // scores, stride 33 -> conflict-free

    const int tid = threadIdx.x;
    const int bh  = blockIdx.y;
    const int row = blockIdx.x * 128 + tid;   // s index of this q row

    const float4* qp = (const float4*)(g_q + ((size_t)bh * SEQ + row) * DK);
    float4 q[16];
    #pragma unroll
    for (int c = 0; c < 16; c++) q[c] = qp[c];

    float4 o[16];
    #pragma unroll
    for (int c = 0; c < 16; c++) o[c] = make_float4(0.f, 0.f, 0.f, 0.f);

    float m = -INFINITY, l = 0.f;

    const float4* Kb = (const float4*)(g_k + (size_t)bh * SEQ * DK);
    const float4* Vb = (const float4*)(g_v + (size_t)bh * SEQ * DK);

    for (int kt = 0; kt < SEQ / KTILE; kt++) {
        __syncthreads();
        // stage K/V tile: 32 rows x 16 float4 = 512 float4 each; 4 per thread
        #pragma unroll
        for (int i = 0; i < 4; i++) {
            int idx = tid + i * 128;          // 0..511
            int r = idx >> 4, c = idx & 15;
            sK[r][c] = Kb[(size_t)(kt * KTILE + r) * 16 + c];
            sV[r][c] = Vb[(size_t)(kt * KTILE + r) * 16 + c];
        }
        __syncthreads();

        // ---- scores: s_j = q . K_j (broadcast LDS, 4 j at a time) ----
        float tmax = -INFINITY;
        #pragma unroll 1
        for (int j0 = 0; j0 < KTILE; j0 += 4) {
            float a0 = 0.f, a1 = 0.f, a2 = 0.f, a3 = 0.f;
            float b0 = 0.f, b1 = 0.f, b2 = 0.f, b3 = 0.f;
            #pragma unroll
            for (int c = 0; c < 16; c += 2) {
                float4 qa = q[c], qb = q[c + 1];
                float4 k0a = sK[j0 + 0][c], k0b = sK[j0 + 0][c + 1];
                float4 k1a = sK[j0 + 1][c], k1b = sK[j0 + 1][c + 1];
                float4 k2a = sK[j0 + 2][c], k2b = sK[j0 + 2][c + 1];
                float4 k3a = sK[j0 + 3][c], k3b = sK[j0 + 3][c + 1];
                a0 += qa.x*k0a.x + qa.y*k0a.y + qa.z*k0a.z + qa.w*k0a.w;
                b0 += qb.x*k0b.x + qb.y*k0b.y + qb.z*k0b.z + qb.w*k0b.w;
                a1 += qa.x*k1a.x + qa.y*k1a.y + qa.z*k1a.z + qa.w*k1a.w;
                b1 += qb.x*k1b.x + qb.y*k1b.y + qb.z*k1b.z + qb.w*k1b.w;
                a2 += qa.x*k2a.x + qa.y*k2a.y + qa.z*k2a.z + qa.w*k2a.w;
                b2 += qb.x*k2b.x + qb.y*k2b.y + qb.z*k2b.z + qb.w*k2b.w;
                a3 += qa.x*k3a.x + qa.y*k3a.y + qa.z*k3a.z + qa.w*k3a.w;
                b3 += qb.x*k3b.x + qb.y*k3b.y + qb.z*k3b.z + qb.w*k3b.w;
            }
            float s0 = a0 + b0, s1 = a1 + b1, s2 = a2 + b2, s3 = a3 + b3;
            sS[tid][j0 + 0] = s0;
            sS[tid][j0 + 1] = s1;
            sS[tid][j0 + 2] = s2;
            sS[tid][j0 + 3] = s3;
            tmax = fmaxf(tmax, fmaxf(fmaxf(s0, s1), fmaxf(s2, s3)));
        }

        // ---- online softmax rescale ----
        float mn = fmaxf(m, tmax);
        float corr = exp2f(m - mn);     // m=-inf on first tile -> corr=0
        l *= corr;
        m = mn;
        #pragma unroll
        for (int c = 0; c < 16; c++) {
            o[c].x *= corr; o[c].y *= corr; o[c].z *= corr; o[c].w *= corr;
        }

        // ---- p = exp2(s - m); o += p * V (broadcast LDS) ----
        #pragma unroll 1
        for (int j0 = 0; j0 < KTILE; j0 += 2) {
            float p0 = exp2f(sS[tid][j0]     - m);
            float p1 = exp2f(sS[tid][j0 + 1] - m);
            l += p0 + p1;
            #pragma unroll
            for (int c = 0; c < 16; c++) {
                float4 v0 = sV[j0][c], v1 = sV[j0 + 1][c];
                o[c].x += p0 * v0.x + p1 * v1.x;
                o[c].y += p0 * v0.y + p1 * v1.y;
                o[c].z += p0 * v0.z + p1 * v1.z;
                o[c].w += p0 * v0.w + p1 * v1.w;
            }
        }
    }

    float inv = 1.0f / l;
    const int b = bh >> 3, h = bh & 7;
    const int t = b * SEQ + row;
    float4* op = (float4*)(g_ao + (size_t)t * EMBED + h * DK);
    #pragma unroll
    for (int c = 0; c < 16; c++) {
        float4 r = o[c];
        r.x *= inv; r.y *= inv; r.z *= inv; r.w *= inv;
        op[c] = r;
    }
}

// ---------------------------------------------------------------------------
// Kernel 3: Y[t][f] = sum_e AO[t][e] * Wc[f][e].  M=8192, N=512, K=512.
// 64x64 block tile, 16-wide K tile, 4x4 per-thread micro tile.
// ---------------------------------------------------------------------------
__global__ void __launch_bounds__(256) proj_kernel(
    const float* __restrict__ Wc, float* __restrict__ out)
{
    __shared__ float As[16][65];   // [k][m]
    __shared__ float Bs[16][65];   // [k][n]

    const int lid = threadIdx.x;
    const int tx = lid & 15, ty = lid >> 4;
    const int m0 = blockIdx.x * 64, n0 = blockIdx.y * 64;

    float acc[4][4];
    #pragma unroll
    for (int i = 0; i < 4; i++)
        #pragma unroll
        for (int j = 0; j < 4; j++) acc[i][j] = 0.f;

    for (int k0 = 0; k0 < EMBED; k0 += 16) {
        #pragma unroll
        for (int i = 0; i < 4; i++) {
            int idx = lid + i * 256;        // 0..1023
            int rr = idx >> 4, kk = idx & 15;
            As[kk][rr] = g_ao[(size_t)(m0 + rr) * EMBED + k0 + kk];
            Bs[kk][rr] = Wc[(size_t)(n0 + rr) * EMBED + k0 + kk];
        }
        __syncthreads();
        #pragma unroll
        for (int kk = 0; kk < 16; kk++) {
            float a[4], bb[4];
            #pragma unroll
            for (int i = 0; i < 4; i++) a[i]  = As[kk][ty * 4 + i];
            #pragma unroll
            for (int j = 0; j < 4; j++) bb[j] = Bs[kk][tx * 4 + j];
            #pragma unroll
            for (int i = 0; i < 4; i++)
                #pragma unroll
                for (int j = 0; j < 4; j++) acc[i][j] += a[i] * bb[j];
        }
        __syncthreads();
    }

    #pragma unroll
    for (int i = 0; i < 4; i++) {
        float* orow = out + (size_t)(m0 + ty * 4 + i) * EMBED + n0 + tx * 4;
        #pragma unroll
        for (int j = 0; j < 4; j++) orow[j] = acc[i][j];
    }
}

// ---------------------------------------------------------------------------
extern "C" void kernel_launch(void* const* d_in, const int* in_sizes, int n_in,
                              void* d_out, int out_size)
{
    (void)in_sizes; (void)n_in; (void)out_size;
    const float* x     = (const float*)d_in[0];
    const float* theta = (const float*)d_in[1];
    const float* Wq    = (const float*)d_in[2];
    const float* Wk    = (const float*)d_in[3];
    const float* Wv    = (const float*)d_in[4];
    const float* Wc    = (const float*)d_in[5];
    float* out = (float*)d_out;

    qkv_kernel<<<TOKENS / 16, 512>>>(x, theta, Wq, Wk, Wv);

    dim3 ag(SEQ / 128, BH);
    attn_kernel<<<ag, 128>>>();

    dim3 pg(TOKENS / 64, EMBED / 64);
    proj_kernel<<<pg, 256>>>(Wc, out);
}

// round 3
// speedup vs baseline: 8.9953x; 8.9953x over previous
#include <cuda_runtime.h>
#include <math.h>

// Problem constants
#define BATCH 4
#define SEQ 2048
#define NWIRES 8
#define EMBED 512
#define HEADS 8
#define DK 64
#define TOKENS (BATCH * SEQ)          // 8192
#define BH (BATCH * HEADS)            // 32

// scale folded into M: 1/sqrt(64) * log2(e)
#define QSCALE (0.125f * 1.4426950408889634f)

// Scratch (device globals; allocation-free rule)
__device__ float g_proj[TOKENS * 8];     // [t][n], proj = cos(x + theta)
__device__ float g_M[HEADS * 64];        // [h][n][a] = QSCALE * Wq_h^T Wk_h
__device__ float g_u[BH * SEQ * 8];      // [bh][s][a] = proj_s^T M_h
__device__ float g_C[EMBED * 64];        // [f][h*8+a] = (Wc_h @ Wv_h)[f][a]
__device__ float g_A[TOKENS * 64];       // [t][h*8+a] = acc/l

// ---------------------------------------------------------------------------
// P1: proj = cos(x + theta)
// ---------------------------------------------------------------------------
__global__ void __launch_bounds__(256) proj_prep_kernel(
    const float* __restrict__ x, const float* __restrict__ theta)
{
    int i = blockIdx.x * 256 + threadIdx.x;      // 0 .. TOKENS*8-1
    g_proj[i] = cosf(x[i] + theta[i & 7]);
}

// ---------------------------------------------------------------------------
// P2: M_h[n][a] = QSCALE * sum_d Wq[h*64+d][n] * Wk[h*64+d][a]
// 8 blocks (heads) x 64 threads
// ---------------------------------------------------------------------------
__global__ void __launch_bounds__(64) m_prep_kernel(
    const float* __restrict__ Wq, const float* __restrict__ Wk)
{
    int h = blockIdx.x;
    int n = threadIdx.x >> 3, a = threadIdx.x & 7;
    float m = 0.f;
    #pragma unroll 8
    for (int d = 0; d < 64; d++)
        m += Wq[(h * 64 + d) * 8 + n] * Wk[(h * 64 + d) * 8 + a];
    g_M[h * 64 + threadIdx.x] = m * QSCALE;
}

// ---------------------------------------------------------------------------
// P3: u[bh][s][a] = sum_n proj[b][s][n] * M_h[n][a]
// grid (SEQ/256, BH), 256 threads
// ---------------------------------------------------------------------------
__global__ void __launch_bounds__(256) u_prep_kernel()
{
    __shared__ float sM[64];
    int bh = blockIdx.y, b = bh >> 3, h = bh & 7;
    int s = blockIdx.x * 256 + threadIdx.x;
    if (threadIdx.x < 64) sM[threadIdx.x] = g_M[h * 64 + threadIdx.x];
    __syncthreads();

    const float* p = g_proj + ((size_t)b * SEQ + s) * 8;
    float pr[8];
    #pragma unroll
    for (int n = 0; n < 8; n++) pr[n] = p[n];

    float* up = g_u + ((size_t)bh * SEQ + s) * 8;
    #pragma unroll
    for (int a = 0; a < 8; a++) {
        float u = 0.f;
        #pragma unroll
        for (int n = 0; n < 8; n++) u += pr[n] * sM[n * 8 + a];
        up[a] = u;
    }
}

// ---------------------------------------------------------------------------
// P4: C[f][h*8+a] = sum_d Wc[f][h*64+d] * Wv[h*64+d][a]
// grid 512 (f), 64 threads
// ---------------------------------------------------------------------------
__global__ void __launch_bounds__(64) c_prep_kernel(
    const float* __restrict__ Wv, const float* __restrict__ Wc)
{
    int f = blockIdx.x;
    int h = threadIdx.x >> 3, a = threadIdx.x & 7;
    float c = 0.f;
    #pragma unroll 8
    for (int d = 0; d < 64; d++)
        c += Wc[(size_t)f * EMBED + h * 64 + d] * Wv[(h * 64 + d) * 8 + a];
    g_C[f * 64 + threadIdx.x] = c;
}

// ---------------------------------------------------------------------------
// Attention in rank-8 space. One thread = one query row i of one (b,h):
//   s_ij = u_i . proj_j  (8 FFMA);  p = exp2(s);  acc8 += p * proj_j;  l += p
// proj for batch b staged in shared in 2 chunks of 1024 rows (32KB).
// grid (SEQ/128, BH), 128 threads.
// ---------------------------------------------------------------------------
__global__ void __launch_bounds__(128) attn_kernel()
{
    __shared__ float4 sp[2048];   // 1024 rows x 2 float4 = 32KB

    const int tid = threadIdx.x;
    const int bh = blockIdx.y, b = bh >> 3, h = bh & 7;
    const int row = blockIdx.x * 128 + tid;

    const float4* up = (const float4*)(g_u + ((size_t)bh * SEQ + row) * 8);
    const float4 u0 = up[0], u1 = up[1];

    float a0 = 0.f, a1 = 0.f, a2 = 0.f, a3 = 0.f;
    float a4 = 0.f, a5 = 0.f, a6 = 0.f, a7 = 0.f;
    float l = 0.f;

    const float4* pb = (const float4*)(g_proj + (size_t)b * SEQ * 8);

    #pragma unroll 1
    for (int c0 = 0; c0 < 2; c0++) {
        __syncthreads();
        #pragma unroll
        for (int i = 0; i < 16; i++)
            sp[tid + i * 128] = pb[c0 * 2048 + tid + i * 128];
        __syncthreads();

        #pragma unroll 1
        for (int jj = 0; jj < 2048; jj += 8) {
            float4 r00 = sp[jj + 0], r01 = sp[jj + 1];
            float4 r10 = sp[jj + 2], r11 = sp[jj + 3];
            float4 r20 = sp[jj + 4], r21 = sp[jj + 5];
            float4 r30 = sp[jj + 6], r31 = sp[jj + 7];

            float s0 = u0.x*r00.x + u0.y*r00.y + u0.z*r00.z + u0.w*r00.w
                     + u1.x*r01.x + u1.y*r01.y + u1.z*r01.z + u1.w*r01.w;
            float s1 = u0.x*r10.x + u0.y*r10.y + u0.z*r10.z + u0.w*r10.w
                     + u1.x*r11.x + u1.y*r11.y + u1.z*r11.z + u1.w*r11.w;
            float s2 = u0.x*r20.x + u0.y*r20.y + u0.z*r20.z + u0.w*r20.w
                     + u1.x*r21.x + u1.y*r21.y + u1.z*r21.z + u1.w*r21.w;
            float s3 = u0.x*r30.x + u0.y*r30.y + u0.z*r30.z + u0.w*r30.w
                     + u1.x*r31.x + u1.y*r31.y + u1.z*r31.z + u1.w*r31.w;

            float p0 = exp2f(s0), p1 = exp2f(s1);
            float p2 = exp2f(s2), p3 = exp2f(s3);
            l += (p0 + p1) + (p2 + p3);

            a0 += p0*r00.x + p1*r10.x + p2*r20.x + p3*r30.x;
            a1 += p0*r00.y + p1*r10.y + p2*r20.y + p3*r30.y;
            a2 += p0*r00.z + p1*r10.z + p2*r20.z + p3*r30.z;
            a3 += p0*r00.w + p1*r10.w + p2*r20.w + p3*r30.w;
            a4 += p0*r01.x + p1*r11.x + p2*r21.x + p3*r31.x;
            a5 += p0*r01.y + p1*r11.y + p2*r21.y + p3*r31.y;
            a6 += p0*r01.z + p1*r11.z + p2*r21.z + p3*r31.z;
            a7 += p0*r01.w + p1*r11.w + p2*r21.w + p3*r31.w;
        }
    }

    const float inv = 1.0f / l;
    float4* outp = (float4*)(g_A + ((size_t)(b * SEQ + row) * 64 + h * 8));
    outp[0] = make_float4(a0 * inv, a1 * inv, a2 * inv, a3 * inv);
    outp[1] = make_float4(a4 * inv, a5 * inv, a6 * inv, a7 * inv);
}

// ---------------------------------------------------------------------------
// Final: out[t][f] = sum_c A[t][c] * C[f][c].  M=8192, N=512, K=64.
// ---------------------------------------------------------------------------
__global__ void __launch_bounds__(256) out_gemm_kernel(float* __restrict__ out)
{
    __shared__ float As[16][65];   // [k][m]
    __shared__ float Bs[16][65];   // [k][n]

    const int lid = threadIdx.x;
    const int tx = lid & 15, ty = lid >> 4;
    const int m0 = blockIdx.x * 64, n0 = blockIdx.y * 64;

    float acc[4][4];
    #pragma unroll
    for (int i = 0; i < 4; i++)
        #pragma unroll
        for (int j = 0; j < 4; j++) acc[i][j] = 0.f;

    #pragma unroll 1
    for (int k0 = 0; k0 < 64; k0 += 16) {
        #pragma unroll
        for (int i = 0; i < 4; i++) {
            int idx = lid + i * 256;        // 0..1023
            int rr = idx >> 4, kk = idx & 15;
            As[kk][rr] = g_A[(size_t)(m0 + rr) * 64 + k0 + kk];
            Bs[kk][rr] = g_C[(size_t)(n0 + rr) * 64 + k0 + kk];
        }
        __syncthreads();
        #pragma unroll
        for (int kk = 0; kk < 16; kk++) {
            float a[4], bb[4];
            #pragma unroll
            for (int i = 0; i < 4; i++) a[i]  = As[kk][ty * 4 + i];
            #pragma unroll
            for (int j = 0; j < 4; j++) bb[j] = Bs[kk][tx * 4 + j];
            #pragma unroll
            for (int i = 0; i < 4; i++)
                #pragma unroll
                for (int j = 0; j < 4; j++) acc[i][j] += a[i] * bb[j];
        }
        __syncthreads();
    }

    #pragma unroll
    for (int i = 0; i < 4; i++) {
        float* orow = out + (size_t)(m0 + ty * 4 + i) * EMBED + n0 + tx * 4;
        #pragma unroll
        for (int j = 0; j < 4; j++) orow[j] = acc[i][j];
    }
}

// ---------------------------------------------------------------------------
extern "C" void kernel_launch(void* const* d_in, const int* in_sizes, int n_in,
                              void* d_out, int out_size)
{
    (void)in_sizes; (void)n_in; (void)out_size;
    const float* x     = (const float*)d_in[0];
    const float* theta = (const float*)d_in[1];
    const float* Wq    = (const float*)d_in[2];
    const float* Wk    = (const float*)d_in[3];
    const float* Wv    = (const float*)d_in[4];
    const float* Wc    = (const float*)d_in[5];
    float* out = (float*)d_out;

    proj_prep_kernel<<<TOKENS * 8 / 256, 256>>>(x, theta);
    m_prep_kernel<<<HEADS, 64>>>(Wq, Wk);
    c_prep_kernel<<<EMBED, 64>>>(Wv, Wc);

    dim3 ug(SEQ / 256, BH);
    u_prep_kernel<<<ug, 256>>>();

    dim3 ag(SEQ / 128, BH);
    attn_kernel<<<ag, 128>>>();

    dim3 gg(TOKENS / 64, EMBED / 64);
    out_gemm_kernel<<<gg, 256>>>(out);
}